// round 15
// baseline (speedup 1.0000x reference)
#include <cuda_runtime.h>
#include <stdint.h>

#define HW 512
#define PLANE (HW*HW)
#define SH 16                 // output rows per warp strip
#define NTHREADS 64
#define NWARPS 2
#define NBLOCKS 1280          // 2560 warp tasks / 2

// gray = round(0.299R + 0.587G + 0.114B) in Q23 fixed point; coeffs sum to 2^23.
#define GC1 2508194u
#define GC2 4924113u
#define GC3 956301u
#define GRND (1u << 22)

__device__ unsigned long long g_sum_sobel;
__device__ unsigned long long g_sum_edge;
__device__ unsigned int       g_count;

__device__ __forceinline__ unsigned q8i(float x) { return (unsigned)(x * 255.0f); }

__device__ __forceinline__ unsigned gray1(unsigned R, unsigned G, unsigned B) {
    return (R * GC1 + G * GC2 + B * GC3 + GRND) >> 23;
}

__device__ __forceinline__ unsigned packq(unsigned a0, unsigned a1,
                                          unsigned a2, unsigned a3) {
    unsigned t, d;
    asm("cvt.pack.sat.u8.s32.b32 %0, %1, %2, 0;"  : "=r"(t) : "r"(a3), "r"(a2));
    asm("cvt.pack.sat.u8.s32.b32 %0, %1, %2, %3;" : "=r"(d) : "r"(a1), "r"(a0), "r"(t));
    return d;
}

__device__ __forceinline__ int reflect512(int i) {
    i = i < 0 ? -i : i;
    return i > 511 ? 1022 - i : i;
}

__device__ __forceinline__ uint32_t smem_u32(const void* p) {
    uint32_t a;
    asm("{ .reg .u64 t; cvta.to.shared.u64 t, %1; cvt.u32.u64 %0, t; }"
        : "=r"(a) : "l"(p));
    return a;
}

#define CP16(dst, src) \
    asm volatile("cp.async.cg.shared.global [%0], [%1], 16;" \
                 :: "r"(dst), "l"(src) : "memory")
#define CP_COMMIT() asm volatile("cp.async.commit_group;" ::: "memory")

__global__ __launch_bounds__(NTHREADS, 10)
void cs_main_kernel(const float* __restrict__ pred, const float* __restrict__ tru,
                    float* __restrict__ out)
{
    // 3-slot per-warp staging ring: [warp][slot][vec][lane], 18 KB total
    __shared__ float4  s_stage[NWARPS][3][6][32];
    __shared__ unsigned s_red[2 * NWARPS];

    const int tid  = threadIdx.x;
    const int lane = tid & 31;
    const int wid  = tid >> 5;
    const int task = blockIdx.x * NWARPS + wid;   // 0..2559
    const int sx   = task % 5;                    // x strip 0..4
    const int rg   = (task / 5) & 31;             // row group 0..31
    const int img  = task / 160;                  // image 0..15
    const int r0   = rg * SH;

    // lane -> packed word index (4 px). Lanes 0 and 31 are halo-only.
    const int word = 30 * sx - 1 + lane;
    const bool ld_ok  = ((unsigned)word <= 127u);
    const bool out_ok = (lane >= 1) && (lane <= 30) && ((unsigned)word <= 127u);
    const bool wedge  = (sx == 0) && (lane == 1);       // image left edge word
    const bool eedge  = (sx == 4) && (word == 127);     // image right edge word

    const float* pb = pred + img * 3 * PLANE + word * 4;
    const float* tb = tru  + img * 3 * PLANE + word * 4;

    const uint32_t st_lane = smem_u32(&s_stage[wid][0][0][lane]);

    // issue 6 cp.async (16B each) for image row (r0-2+j) into ring slot
    auto issuerow = [&](int j, int slot) {
        const int gy = reflect512(r0 - 2 + j);
        const float* p = pb + gy * HW;
        const float* t = tb + gy * HW;
        const uint32_t d = st_lane + slot * 3072;   // slot stride 6*32*16
        if (ld_ok) {
            CP16(d +    0, p);
            CP16(d +  512, p + PLANE);
            CP16(d + 1024, p + 2 * PLANE);
            CP16(d + 1536, t);
            CP16(d + 2048, t + PLANE);
            CP16(d + 2560, t + 2 * PLANE);
        }
        CP_COMMIT();
    };

    // convert slot -> packed gray + rgb words
    auto convslot = [&](int slot, unsigned& gP, unsigned& gT,
                        unsigned* rP, unsigned* rT) {
        const float4* S = &s_stage[wid][slot][0][lane];  // vec stride = 32
        {
            const float4 A = S[0], B = S[32], C = S[64];
            unsigned R0=q8i(A.x),R1=q8i(A.y),R2=q8i(A.z),R3=q8i(A.w);
            unsigned G0=q8i(B.x),G1=q8i(B.y),G2=q8i(B.z),G3=q8i(B.w);
            unsigned B0=q8i(C.x),B1=q8i(C.y),B2=q8i(C.z),B3=q8i(C.w);
            rP[0]=packq(R0,R1,R2,R3); rP[1]=packq(G0,G1,G2,G3); rP[2]=packq(B0,B1,B2,B3);
            gP = packq(gray1(R0,G0,B0), gray1(R1,G1,B1),
                       gray1(R2,G2,B2), gray1(R3,G3,B3));
        }
        {
            const float4 A = S[96], B = S[128], C = S[160];
            unsigned R0=q8i(A.x),R1=q8i(A.y),R2=q8i(A.z),R3=q8i(A.w);
            unsigned G0=q8i(B.x),G1=q8i(B.y),G2=q8i(B.z),G3=q8i(B.w);
            unsigned B0=q8i(C.x),B1=q8i(C.y),B2=q8i(C.z),B3=q8i(C.w);
            rT[0]=packq(R0,R1,R2,R3); rT[1]=packq(G0,G1,G2,G3); rT[2]=packq(B0,B1,B2,B3);
            gT = packq(gray1(R0,G0,B0), gray1(R1,G1,B1),
                       gray1(R2,G2,B2), gray1(R3,G3,B3));
        }
    };

    auto sobelrow = [&](unsigned gup, unsigned gmid, unsigned gdn) -> unsigned {
        const unsigned gp = __shfl_up_sync(0xFFFFFFFFu, gmid, 1);
        const unsigned gn = __shfl_down_sync(0xFFFFFFFFu, gmid, 1);
        unsigned W4 = __funnelshift_r(gp, gmid, 24);
        unsigned E4 = __funnelshift_r(gmid, gn, 8);
        if (wedge) W4 = __byte_perm(gmid, 0, 0x2101);   // reflect at x=0
        if (eedge) E4 = __byte_perm(gmid, 0, 0x2321);   // reflect at x=511
        const unsigned sx4 = __vabsdiffu4(E4, W4);
        const unsigned sy4 = __vabsdiffu4(gdn, gup);
        const unsigned avg = __vavgu4(sx4, sy4);
        const unsigned cor = (sx4 ^ sy4) & avg & 0x01010101u;
        return avg - cor;
    };

    auto dilmask = [&](unsigned vm) -> unsigned {
        const unsigned vp = __shfl_up_sync(0xFFFFFFFFu, vm, 1);
        const unsigned vn = __shfl_down_sync(0xFFFFFFFFu, vm, 1);
        unsigned Wv = __funnelshift_r(vp, vm, 24);
        unsigned Ev = __funnelshift_r(vm, vn, 8);
        if (wedge) Wv = __byte_perm(vm, 0, 0x2101);
        if (eedge) Ev = __byte_perm(vm, 0, 0x2321);
        return __vcmpgtu4(__vmaxu4(vm, __vmaxu4(Wv, Ev)), 0x0A0A0A0Au);
    };

    // ---- prologue: 3 rows in flight (prefetch distance 2) ----
    issuerow(0, 0);
    issuerow(1, 1);
    issuerow(2, 2);

    unsigned gp1, gp2, gt1, gt2;         // gray rows j-2, j-1
    unsigned sp1, sp2, st1, st2;         // sobel rows j-3, j-2
    unsigned rpB[3], rpC[3], rtB[3], rtC[3];  // rgb rows j-1, j-2
    unsigned acc_s = 0, acc_e = 0;

    // ---- fully-unrolled streaming loop ----
    #pragma unroll
    for (int j = 0; j <= SH + 3; ++j) {
        // wait until row j's group has landed (compile-time immediates)
        if (j <= SH + 1)      asm volatile("cp.async.wait_group 2;" ::: "memory");
        else if (j == SH + 2) asm volatile("cp.async.wait_group 1;" ::: "memory");
        else                  asm volatile("cp.async.wait_group 0;" ::: "memory");

        unsigned gnp, gnt, rnP[3], rnT[3];
        convslot(j % 3, gnp, gnt, rnP, rnT);              // row j
        if (j + 3 <= SH + 3) issuerow(j + 3, j % 3);      // refill freed slot

        if (j >= 2) {
            const unsigned snp = sobelrow(gp1, gp2, gnp); // sobel row j-1
            const unsigned snt = sobelrow(gt1, gt2, gnt);
            if (j >= 4 && out_ok) {
                acc_s = __dp4a(__vabsdiffu4(sp2, st2), 0x01010101u, acc_s);
                const unsigned vmp = __vmaxu4(sp1, __vmaxu4(sp2, snp));
                const unsigned vmt = __vmaxu4(st1, __vmaxu4(st2, snt));
                const unsigned kp = dilmask(vmp);
                const unsigned kt = dilmask(vmt);
                const unsigned both = kp & kt;
                const unsigned onp  = kp & ~kt;
                const unsigned ont  = kt & ~kp;
                #pragma unroll
                for (int c = 0; c < 3; c++) {
                    const unsigned val = (__vabsdiffu4(rpC[c], rtC[c]) & both) |
                                         (rpC[c] & onp) | (rtC[c] & ont);
                    acc_e = __dp4a(val, 0x01010101u, acc_e);
                }
            } else if (j >= 4) {
                // keep shuffle participation uniform across the warp
                (void)dilmask(__vmaxu4(sp1, __vmaxu4(sp2, snp)));
                (void)dilmask(__vmaxu4(st1, __vmaxu4(st2, snt)));
            }
            sp1 = sp2; sp2 = snp; st1 = st2; st2 = snt;
        }
        gp1 = gp2; gp2 = gnp; gt1 = gt2; gt2 = gnt;
        #pragma unroll
        for (int c = 0; c < 3; c++) {
            rpC[c] = rpB[c]; rpB[c] = rnP[c];
            rtC[c] = rtB[c]; rtB[c] = rnT[c];
        }
    }

    // ---- exact integer reduction + last-block finalize ----
    const unsigned ws = __reduce_add_sync(0xFFFFFFFFu, acc_s);
    const unsigned we = __reduce_add_sync(0xFFFFFFFFu, acc_e);
    if (lane == 0) { s_red[wid] = ws; s_red[NWARPS + wid] = we; }
    __syncthreads();
    if (wid == 0) {
        unsigned a = (lane < NWARPS) ? s_red[lane] : 0u;
        unsigned e = (lane < NWARPS) ? s_red[NWARPS + lane] : 0u;
        a = __reduce_add_sync(0xFFFFFFFFu, a);
        e = __reduce_add_sync(0xFFFFFFFFu, e);
        if (lane == 0) {
            atomicAdd(&g_sum_sobel, (unsigned long long)a);
            atomicAdd(&g_sum_edge,  (unsigned long long)e);
            __threadfence();
            const unsigned old = atomicAdd(&g_count, 1u);
            if (old == NBLOCKS - 1) {
                const unsigned long long ss = atomicAdd(&g_sum_sobel, 0ULL);
                const unsigned long long se = atomicAdd(&g_sum_edge, 0ULL);
                const double N = 16.0 * 512.0 * 512.0;
                out[0] = (float)((double)ss / (255.0 * N));
                out[1] = (float)((double)se / (255.0 * N * 3.0));
                g_sum_sobel = 0ULL;
                g_sum_edge  = 0ULL;
                __threadfence();
                g_count = 0u;
            }
        }
    }
}

extern "C" void kernel_launch(void* const* d_in, const int* in_sizes, int n_in,
                              void* d_out, int out_size) {
    const float* y_pred = (const float*)d_in[0];
    const float* y_true = (const float*)d_in[1];
    float* out = (float*)d_out;

    cs_main_kernel<<<NBLOCKS, NTHREADS>>>(y_pred, y_true, out);
}

// round 16
// speedup vs baseline: 1.4194x; 1.4194x over previous
#include <cuda_runtime.h>
#include <stdint.h>

#define HW 512
#define PLANE (HW*HW)
#define SH 16                 // output rows per warp strip
#define NTHREADS 64
#define NWARPS 2
#define NBLOCKS 1280          // 2560 warp tasks / 2

// gray = round(0.299R + 0.587G + 0.114B) in Q23 fixed point; coeffs sum to 2^23.
#define GC1 2508194u
#define GC2 4924113u
#define GC3 956301u
#define GRND (1u << 22)

__device__ unsigned long long g_sum_sobel;
__device__ unsigned long long g_sum_edge;
__device__ unsigned int       g_count;

// Inputs uniform [0,1): x*255 in [0,255) -> uint8 quantize == trunc toward 0.
__device__ __forceinline__ unsigned q8i(float x) { return (unsigned)(x * 255.0f); }

__device__ __forceinline__ unsigned gray1(unsigned R, unsigned G, unsigned B) {
    return (R * GC1 + G * GC2 + B * GC3 + GRND) >> 23;
}

// pack 4 byte-valued ints into one word via cvt.pack (cvt pipe, not ALU)
__device__ __forceinline__ unsigned packq(unsigned a0, unsigned a1,
                                          unsigned a2, unsigned a3) {
    unsigned t, d;
    asm("cvt.pack.sat.u8.s32.b32 %0, %1, %2, 0;"  : "=r"(t) : "r"(a3), "r"(a2));
    asm("cvt.pack.sat.u8.s32.b32 %0, %1, %2, %3;" : "=r"(d) : "r"(a1), "r"(a0), "r"(t));
    return d;
}

__device__ __forceinline__ int reflect512(int i) {
    i = i < 0 ? -i : i;
    return i > 511 ? 1022 - i : i;
}

#define PF_L2(p) asm volatile("prefetch.global.L2 [%0];" :: "l"(p))

__global__ __launch_bounds__(NTHREADS, 10)
void cs_main_kernel(const float* __restrict__ pred, const float* __restrict__ tru,
                    float* __restrict__ out)
{
    __shared__ unsigned s_red[2 * NWARPS];

    const int tid  = threadIdx.x;
    const int lane = tid & 31;
    const int wid  = tid >> 5;
    const int task = blockIdx.x * NWARPS + wid;   // 0..2559
    const int sx   = task % 5;                    // x strip 0..4
    const int rg   = (task / 5) & 31;             // row group 0..31
    const int img  = task / 160;                  // image 0..15
    const int r0   = rg * SH;

    // lane -> packed word index (4 px). Lanes 0 and 31 are halo-only.
    const int word = 30 * sx - 1 + lane;
    const bool ld_ok  = ((unsigned)word <= 127u);
    const bool out_ok = (lane >= 1) && (lane <= 30) && ((unsigned)word <= 127u);
    const bool wedge  = (sx == 0) && (lane == 1);       // image left edge word
    const bool eedge  = (sx == 4) && (word == 127);     // image right edge word

    const float* pb = pred + img * 3 * PLANE + word * 4;
    const float* tb = tru  + img * 3 * PLANE + word * 4;

    auto loadrow = [&](int j, float4* F) {
        const int gy = reflect512(r0 - 2 + j);
        const float* p = pb + gy * HW;
        const float* t = tb + gy * HW;
        if (ld_ok) {
            F[0] = *(const float4*)(p);
            F[1] = *(const float4*)(p + PLANE);
            F[2] = *(const float4*)(p + 2 * PLANE);
            F[3] = *(const float4*)(t);
            F[4] = *(const float4*)(t + PLANE);
            F[5] = *(const float4*)(t + 2 * PLANE);
        }
    };

    // zero-register latency lever: pull row j's lines into L2 ahead of time
    auto prefrow = [&](int j) {
        const int gy = reflect512(r0 - 2 + j);
        const float* p = pb + gy * HW;
        const float* t = tb + gy * HW;
        if (ld_ok) {
            PF_L2(p);              PF_L2(p + PLANE);      PF_L2(p + 2 * PLANE);
            PF_L2(t);              PF_L2(t + PLANE);      PF_L2(t + 2 * PLANE);
        }
    };

    auto convrow = [&](const float4* F, unsigned& gP, unsigned& gT,
                       unsigned* rP, unsigned* rT) {
        {
            unsigned R0=q8i(F[0].x),R1=q8i(F[0].y),R2=q8i(F[0].z),R3=q8i(F[0].w);
            unsigned G0=q8i(F[1].x),G1=q8i(F[1].y),G2=q8i(F[1].z),G3=q8i(F[1].w);
            unsigned B0=q8i(F[2].x),B1=q8i(F[2].y),B2=q8i(F[2].z),B3=q8i(F[2].w);
            rP[0]=packq(R0,R1,R2,R3); rP[1]=packq(G0,G1,G2,G3); rP[2]=packq(B0,B1,B2,B3);
            gP = packq(gray1(R0,G0,B0), gray1(R1,G1,B1),
                       gray1(R2,G2,B2), gray1(R3,G3,B3));
        }
        {
            unsigned R0=q8i(F[3].x),R1=q8i(F[3].y),R2=q8i(F[3].z),R3=q8i(F[3].w);
            unsigned G0=q8i(F[4].x),G1=q8i(F[4].y),G2=q8i(F[4].z),G3=q8i(F[4].w);
            unsigned B0=q8i(F[5].x),B1=q8i(F[5].y),B2=q8i(F[5].z),B3=q8i(F[5].w);
            rT[0]=packq(R0,R1,R2,R3); rT[1]=packq(G0,G1,G2,G3); rT[2]=packq(B0,B1,B2,B3);
            gT = packq(gray1(R0,G0,B0), gray1(R1,G1,B1),
                       gray1(R2,G2,B2), gray1(R3,G3,B3));
        }
    };

    // sobel of the row held in gmid (gup/gdn: rows above/below), exact half-even.
    auto sobelrow = [&](unsigned gup, unsigned gmid, unsigned gdn) -> unsigned {
        const unsigned gp = __shfl_up_sync(0xFFFFFFFFu, gmid, 1);
        const unsigned gn = __shfl_down_sync(0xFFFFFFFFu, gmid, 1);
        unsigned W4 = __funnelshift_r(gp, gmid, 24);
        unsigned E4 = __funnelshift_r(gmid, gn, 8);
        if (wedge) W4 = __byte_perm(gmid, 0, 0x2101);   // reflect at x=0
        if (eedge) E4 = __byte_perm(gmid, 0, 0x2321);   // reflect at x=511
        const unsigned sx4 = __vabsdiffu4(E4, W4);
        const unsigned sy4 = __vabsdiffu4(gdn, gup);
        const unsigned avg = __vavgu4(sx4, sy4);
        const unsigned cor = (sx4 ^ sy4) & avg & 0x01010101u;
        return avg - cor;
    };

    auto dilmask = [&](unsigned vm) -> unsigned {
        const unsigned vp = __shfl_up_sync(0xFFFFFFFFu, vm, 1);
        const unsigned vn = __shfl_down_sync(0xFFFFFFFFu, vm, 1);
        unsigned Wv = __funnelshift_r(vp, vm, 24);
        unsigned Ev = __funnelshift_r(vm, vn, 8);
        if (wedge) Wv = __byte_perm(vm, 0, 0x2101);
        if (eedge) Ev = __byte_perm(vm, 0, 0x2321);
        return __vcmpgtu4(__vmaxu4(vm, __vmaxu4(Wv, Ev)), 0x0A0A0A0Au);
    };

    float4 Fc[6], Fn[6];
    unsigned gp1, gp2, gt1, gt2;         // gray rows j-2, j-1
    unsigned sp1, sp2, st1, st2;         // sobel rows j-3, j-2
    unsigned rpA[3], rpB[3], rpC[3];     // rgb pred rows j, j-1, j-2
    unsigned rtA[3], rtB[3], rtC[3];
    unsigned acc_s = 0, acc_e = 0;

    // ---- prologue: rows 0,1 (+ L2 prefetch of rows 2,3) ----
    loadrow(0, Fc);
    loadrow(1, Fn);
    prefrow(2);
    prefrow(3);
    convrow(Fc, gp1, gt1, rpC, rtC);                  // row 0
    #pragma unroll
    for (int q = 0; q < 6; q++) Fc[q] = Fn[q];
    loadrow(2, Fn);
    prefrow(4);
    convrow(Fc, gp2, gt2, rpB, rtB);                  // row 1
    #pragma unroll
    for (int q = 0; q < 6; q++) Fc[q] = Fn[q];        // Fc = row 2

    // ---- j = 2,3: build sobel ring, no loss yet ----
    #pragma unroll
    for (int j = 2; j <= 3; ++j) {
        loadrow(j + 1, Fn);
        prefrow(j + 3);
        unsigned gnp, gnt;
        convrow(Fc, gnp, gnt, rpA, rtA);              // row j
        const unsigned snp = sobelrow(gp1, gp2, gnp); // sobel row j-1
        const unsigned snt = sobelrow(gt1, gt2, gnt);
        sp1 = sp2; sp2 = snp; st1 = st2; st2 = snt;
        gp1 = gp2; gp2 = gnp; gt1 = gt2; gt2 = gnt;
        #pragma unroll
        for (int c = 0; c < 3; c++) {
            rpC[c] = rpB[c]; rpB[c] = rpA[c];
            rtC[c] = rtB[c]; rtB[c] = rtA[c];
        }
        #pragma unroll
        for (int q = 0; q < 6; q++) Fc[q] = Fn[q];
    }

    // ---- steady loop: j = 4 .. SH+3, loss for image row r0 + j - 4 ----
    #pragma unroll
    for (int j = 4; j <= SH + 3; ++j) {
        if (j < SH + 3) { loadrow(j + 1, Fn); }
        if (j + 3 <= SH + 3) prefrow(j + 3);
        unsigned gnp, gnt;
        convrow(Fc, gnp, gnt, rpA, rtA);              // row j
        const unsigned snp = sobelrow(gp1, gp2, gnp); // sobel row j-1
        const unsigned snt = sobelrow(gt1, gt2, gnt);
        // vm row j-2 = max(sobel rows j-3, j-2, j-1)
        const unsigned vmp = __vmaxu4(sp1, __vmaxu4(sp2, snp));
        const unsigned vmt = __vmaxu4(st1, __vmaxu4(st2, snt));
        const unsigned kp = dilmask(vmp);
        const unsigned kt = dilmask(vmt);
        if (out_ok) {
            acc_s = __dp4a(__vabsdiffu4(sp2, st2), 0x01010101u, acc_s);
            const unsigned both = kp & kt;
            const unsigned onp  = kp & ~kt;
            const unsigned ont  = kt & ~kp;
            #pragma unroll
            for (int c = 0; c < 3; c++) {
                const unsigned val = (__vabsdiffu4(rpC[c], rtC[c]) & both) |
                                     (rpC[c] & onp) | (rtC[c] & ont);
                acc_e = __dp4a(val, 0x01010101u, acc_e);
            }
        }
        sp1 = sp2; sp2 = snp; st1 = st2; st2 = snt;
        gp1 = gp2; gp2 = gnp; gt1 = gt2; gt2 = gnt;
        #pragma unroll
        for (int c = 0; c < 3; c++) {
            rpC[c] = rpB[c]; rpB[c] = rpA[c];
            rtC[c] = rtB[c]; rtB[c] = rtA[c];
        }
        #pragma unroll
        for (int q = 0; q < 6; q++) Fc[q] = Fn[q];
    }

    // ---- exact integer reduction + last-block finalize ----
    const unsigned ws = __reduce_add_sync(0xFFFFFFFFu, acc_s);
    const unsigned we = __reduce_add_sync(0xFFFFFFFFu, acc_e);
    if (lane == 0) { s_red[wid] = ws; s_red[NWARPS + wid] = we; }
    __syncthreads();
    if (wid == 0) {
        unsigned a = (lane < NWARPS) ? s_red[lane] : 0u;
        unsigned e = (lane < NWARPS) ? s_red[NWARPS + lane] : 0u;
        a = __reduce_add_sync(0xFFFFFFFFu, a);
        e = __reduce_add_sync(0xFFFFFFFFu, e);
        if (lane == 0) {
            atomicAdd(&g_sum_sobel, (unsigned long long)a);
            atomicAdd(&g_sum_edge,  (unsigned long long)e);
            __threadfence();
            const unsigned old = atomicAdd(&g_count, 1u);
            if (old == NBLOCKS - 1) {
                const unsigned long long ss = atomicAdd(&g_sum_sobel, 0ULL);
                const unsigned long long se = atomicAdd(&g_sum_edge, 0ULL);
                const double N = 16.0 * 512.0 * 512.0;
                out[0] = (float)((double)ss / (255.0 * N));
                out[1] = (float)((double)se / (255.0 * N * 3.0));
                g_sum_sobel = 0ULL;
                g_sum_edge  = 0ULL;
                __threadfence();
                g_count = 0u;
            }
        }
    }
}

extern "C" void kernel_launch(void* const* d_in, const int* in_sizes, int n_in,
                              void* d_out, int out_size) {
    const float* y_pred = (const float*)d_in[0];
    const float* y_true = (const float*)d_in[1];
    float* out = (float*)d_out;

    cs_main_kernel<<<NBLOCKS, NTHREADS>>>(y_pred, y_true, out);
}